// round 6
// baseline (speedup 1.0000x reference)
#include <cuda_runtime.h>
#include <cuda_fp8.h>
#include <cuda_bf16.h>

#define S_N     32
#define NHEAD   32
#define HDIM    128
#define NKVH    8
#define GQ      4
#define BSZ     16
#define MBLK    128
#define NSPLIT  16
#define CHUNK   128
#define TILE    32
#define ROWB    136          // bf16 elems per smem row (272B: 16B-aligned, conflict-free)
#define ATTN_SCALE 0.08838834764831845f
#define NEG_BIG   -3.402823466e38f

// split-KV partial scratch (static device memory: allocation-free)
__device__ float g_po[S_N][NKVH][NSPLIT][GQ][HDIM];
__device__ float g_pm[S_N][NKVH][NSPLIT][GQ];
__device__ float g_pl[S_N][NKVH][NSPLIT][GQ];

// Exact emulation of reference dequant chain, returning the two packed bf16x2
// words for 4 elements: bf16( f32(e4m3_satfinite_rn(c)) * scale )
__device__ __forceinline__ uint2 dq4_bf(float4 c, float s) {
    float2 a = make_float2(c.x, c.y);
    float2 b = make_float2(c.z, c.w);
    __nv_fp8x2_storage_t p0 = __nv_cvt_float2_to_fp8x2(a, __NV_SATFINITE, __NV_E4M3);
    __nv_fp8x2_storage_t p1 = __nv_cvt_float2_to_fp8x2(b, __NV_SATFINITE, __NV_E4M3);
    __half2_raw h0 = __nv_cvt_fp8x2_to_halfraw2(p0, __NV_E4M3);
    __half2_raw h1 = __nv_cvt_fp8x2_to_halfraw2(p1, __NV_E4M3);
    float2 f0 = __half22float2(*reinterpret_cast<__half2*>(&h0));
    float2 f1 = __half22float2(*reinterpret_cast<__half2*>(&h1));
    f0.x *= s; f0.y *= s; f1.x *= s; f1.y *= s;
    __nv_bfloat162 bb0 = __float22bfloat162_rn(f0);
    __nv_bfloat162 bb1 = __float22bfloat162_rn(f1);
    uint2 r;
    r.x = *reinterpret_cast<unsigned*>(&bb0);
    r.y = *reinterpret_cast<unsigned*>(&bb1);
    return r;
}

// bf16x2 word -> two exact f32 (bf16 value = upper 16 bits of f32)
__device__ __forceinline__ float bflo(unsigned u) { return __uint_as_float(u << 16); }
__device__ __forceinline__ float bfhi(unsigned u) { return __uint_as_float(u & 0xFFFF0000u); }

__global__ void __launch_bounds__(128)
attn_main_kernel(const float* __restrict__ q, const float* __restrict__ knew,
                 const float* __restrict__ vnew, const float* __restrict__ kcache,
                 const float* __restrict__ vcache, const float* __restrict__ kscale_p,
                 const float* __restrict__ vscale_p, const int* __restrict__ btab,
                 const int* __restrict__ clen)
{
    const int split = blockIdx.x;
    const int h     = blockIdx.y;
    const int s     = blockIdx.z;
    const int ctx   = clen[s];
    const int c0    = split * CHUNK;
    if (c0 >= ctx) return;
    const int nvalid = min(CHUNK, ctx - c0);
    const int ntile  = (nvalid + TILE - 1) / TILE;

    __shared__ unsigned short kt[TILE][ROWB];   // dequantized K tile (bf16)
    __shared__ unsigned short vt[TILE][ROWB];   // dequantized V tile (bf16)
    __shared__ float qs[GQ * HDIM];

    const int t = threadIdx.x;
    const int w = t >> 5;     // warp = query head within GQA group
    const int l = t & 31;     // lane

    // stage Q (512 floats, raw f32 as in reference)
    ((float4*)qs)[t] = ((const float4*)(q + (size_t)s * (NHEAD * HDIM)
                                          + (size_t)h * (GQ * HDIM)))[t];
    const float ks = kscale_p[h];
    const float vs = vscale_p[h];
    const float* kp = knew + (size_t)s * (NKVH * HDIM) + h * HDIM + l * 4;
    const float* vp = vnew + (size_t)s * (NKVH * HDIM) + h * HDIM + l * 4;

    // hoist the chunk's 8 cache-block indices (independent LDGs, once per CTA)
    int blkArr[CHUNK / BSZ];
    #pragma unroll
    for (int j = 0; j < CHUNK / BSZ; ++j)
        blkArr[j] = btab[s * MBLK + (c0 >> 4) + j];

    float  m    = NEG_BIG;
    float  lsum = 0.f;
    float4 o    = make_float4(0.f, 0.f, 0.f, 0.f);

    float4 kpre[8], vpre[8];   // prefetch buffer: this thread's 8 rows of next tile

    // macro-ish lambdas keep LDG issue order tight
    auto load_tile = [&](int tb, float4* kr, float4* vr) {
        const int base = c0 + tb * TILE;
        #pragma unroll
        for (int i = 0; i < 8; ++i) {
            const int pl = i * 4 + w;
            const int P  = base + pl;                  // < 2048 always: safe loads
            const long long blk  = (long long)blkArr[tb * 2 + (pl >> 4)];
            const long long roff = ((blk * BSZ + (P & 15)) * NKVH + h) * (long long)HDIM;
            kr[i] = ((const float4*)(kcache + roff))[l];
            vr[i] = ((const float4*)(vcache + roff))[l];
        }
        const int newrow = (ctx - 1) - base;           // tile-local row of new token
        if (newrow >= 0 && newrow < TILE && ((newrow - w) & 3) == 0) {
            const int i = (newrow - w) >> 2;
            float4 kn4 = *(const float4*)kp;
            float4 vn4 = *(const float4*)vp;
            kpre[i].x = 0; // dummy to keep compiler honest (overwritten below)
            kr[i] = make_float4(__fdiv_rn(kn4.x, ks), __fdiv_rn(kn4.y, ks),
                                __fdiv_rn(kn4.z, ks), __fdiv_rn(kn4.w, ks));
            vr[i] = make_float4(__fdiv_rn(vn4.x, vs), __fdiv_rn(vn4.y, vs),
                                __fdiv_rn(vn4.z, vs), __fdiv_rn(vn4.w, vs));
        }
    };
    auto store_tile = [&](const float4* kr, const float4* vr) {
        #pragma unroll
        for (int i = 0; i < 8; ++i) {
            const int pl = i * 4 + w;
            *(uint2*)&kt[pl][l * 4] = dq4_bf(kr[i], ks);
            *(uint2*)&vt[pl][l * 4] = dq4_bf(vr[i], vs);
        }
    };

    // prologue: stage tile 0
    load_tile(0, kpre, vpre);
    store_tile(kpre, vpre);
    __syncthreads();

    for (int tb = 0; tb < ntile; ++tb) {
        const int base = c0 + tb * TILE;
        const bool more = (tb + 1 < ntile);

        // issue next tile's global loads NOW (latency overlapped with compute below)
        if (more) load_tile(tb + 1, kpre, vpre);

        // ---- scores: warp w = head w, lane l = position l (row l of K, 8 bf16 per LDS.128)
        float4 acc = make_float4(0.f, 0.f, 0.f, 0.f);
        #pragma unroll
        for (int d8 = 0; d8 < 16; ++d8) {
            const uint4  kq = *(const uint4*)&kt[l][d8 * 8];
            const float4 qa = *(const float4*)&qs[w * HDIM + d8 * 8];
            const float4 qb = *(const float4*)&qs[w * HDIM + d8 * 8 + 4];
            acc.x += bflo(kq.x) * qa.x; acc.y += bfhi(kq.x) * qa.y;
            acc.z += bflo(kq.y) * qa.z; acc.w += bfhi(kq.y) * qa.w;
            acc.x += bflo(kq.z) * qb.x; acc.y += bfhi(kq.z) * qb.y;
            acc.z += bflo(kq.w) * qb.z; acc.w += bfhi(kq.w) * qb.w;
        }
        float sc = ((acc.x + acc.y) + (acc.z + acc.w)) * ATTN_SCALE;
        if (base + l >= ctx) sc = NEG_BIG;

        // online softmax (per warp)
        float tm = sc;
        #pragma unroll
        for (int off = 16; off > 0; off >>= 1)
            tm = fmaxf(tm, __shfl_xor_sync(0xFFFFFFFFu, tm, off));
        const float mnew  = fmaxf(m, tm);
        const float alpha = __expf(m - mnew);
        const float p     = __expf(sc - mnew);   // masked lanes underflow to 0
        float tsum = p;
        #pragma unroll
        for (int off = 16; off > 0; off >>= 1)
            tsum += __shfl_xor_sync(0xFFFFFFFFu, tsum, off);
        lsum = lsum * alpha + tsum;
        m = mnew;

        // ---- accumulate O: lane l owns dims 4l..4l+3; weights broadcast by shuffle
        o.x *= alpha; o.y *= alpha; o.z *= alpha; o.w *= alpha;
        #pragma unroll
        for (int pp = 0; pp < 32; ++pp) {
            const float wgt = __shfl_sync(0xFFFFFFFFu, p, pp);
            const uint2 vq  = *(const uint2*)&vt[pp][l * 4];
            o.x += wgt * bflo(vq.x); o.y += wgt * bfhi(vq.x);
            o.z += wgt * bflo(vq.y); o.w += wgt * bfhi(vq.y);
        }
        __syncthreads();   // all warps done reading smem tile tb

        if (more) {
            store_tile(kpre, vpre);   // consumes the in-flight LDGs
            __syncthreads();          // smem tile tb+1 ready
        }
    }

    *(float4*)&g_po[s][h][split][w][l * 4] = o;
    if (l == 0) { g_pm[s][h][split][w] = m; g_pl[s][h][split][w] = lsum; }
}

// block per (kvh, seq); warp w = GQA sub-head; lanes parallelize splits then dims
__global__ void __launch_bounds__(128)
attn_combine_kernel(const int* __restrict__ clen, float* __restrict__ out)
{
    const int h = blockIdx.x;
    const int s = blockIdx.y;
    const int g = threadIdx.x >> 5;
    const int l = threadIdx.x & 31;
    const int ctx = clen[s];
    const int nsp = (ctx + CHUNK - 1) / CHUNK;   // 1..16

    // lane i holds split i's (m, l) partials
    float mi = (l < nsp) ? g_pm[s][h][l][g] : NEG_BIG;
    float li = (l < nsp) ? g_pl[s][h][l][g] : 0.f;
    float M = mi;
    #pragma unroll
    for (int off = 16; off > 0; off >>= 1)
        M = fmaxf(M, __shfl_xor_sync(0xFFFFFFFFu, M, off));
    const float wi = __expf(mi - M);     // 0 for inactive lanes
    float L = wi * li;
    #pragma unroll
    for (int off = 16; off > 0; off >>= 1)
        L += __shfl_xor_sync(0xFFFFFFFFu, L, off);

    // lane l accumulates dims 4l..4l+3; 16 predicated independent loads (high MLP)
    float4 acc = make_float4(0.f, 0.f, 0.f, 0.f);
    #pragma unroll
    for (int i = 0; i < NSPLIT; ++i) {
        if (i < nsp) {
            const float wgt = __shfl_sync(0xFFFFFFFFu, wi, i);
            const float4 pv = *(const float4*)&g_po[s][h][i][g][l * 4];
            acc.x += wgt * pv.x; acc.y += wgt * pv.y;
            acc.z += wgt * pv.z; acc.w += wgt * pv.w;
        }
    }
    const float inv = 1.f / L;
    float4 r = make_float4(acc.x * inv, acc.y * inv, acc.z * inv, acc.w * inv);
    *(float4*)(out + (size_t)s * (NHEAD * HDIM)
                   + (size_t)(h * GQ + g) * HDIM + l * 4) = r;
}

extern "C" void kernel_launch(void* const* d_in, const int* in_sizes, int n_in,
                              void* d_out, int out_size) {
    (void)in_sizes; (void)n_in; (void)out_size;
    const float* q    = (const float*)d_in[0];
    const float* k    = (const float*)d_in[1];
    const float* v    = (const float*)d_in[2];
    const float* kc   = (const float*)d_in[3];
    const float* vc   = (const float*)d_in[4];
    const float* ksc  = (const float*)d_in[5];
    const float* vsc  = (const float*)d_in[6];
    // d_in[7] slot_mapping: unused (position ctx-1 substitution is equivalent)
    const int*   btab = (const int*)d_in[8];   // JAX x64 disabled -> int32
    const int*   clen = (const int*)d_in[9];

    dim3 g1(NSPLIT, NKVH, S_N);
    attn_main_kernel<<<g1, 128>>>(q, k, v, kc, vc, ksc, vsc, btab, clen);
    dim3 g2(NKVH, S_N);
    attn_combine_kernel<<<g2, 128>>>(clen, (float*)d_out);
}

// round 7
// speedup vs baseline: 1.8142x; 1.8142x over previous
#include <cuda_runtime.h>
#include <cuda_fp8.h>
#include <cuda_bf16.h>

#define S_N     32
#define NHEAD   32
#define HDIM    128
#define NKVH    8
#define GQ      4
#define BSZ     16
#define MBLK    128
#define NSPLIT  16
#define CHUNK   128
#define TILE    32
#define ROWB    136          // bf16 elems per smem row (272B: 16B-aligned, conflict-free)
#define ATTN_SCALE 0.08838834764831845f
#define NEG_BIG   -3.402823466e38f

// split-KV partial scratch (static device memory: allocation-free)
__device__ float g_po[S_N][NKVH][NSPLIT][GQ][HDIM];
__device__ float g_pm[S_N][NKVH][NSPLIT][GQ];
__device__ float g_pl[S_N][NKVH][NSPLIT][GQ];
__device__ int   g_cnt[S_N][NKVH];   // zero-init; protocol restores 0 every run

// Exact emulation of reference dequant chain, returning the two packed bf16x2
// words for 4 elements: bf16( f32(e4m3_satfinite_rn(c)) * scale )
__device__ __forceinline__ uint2 dq4_bf(float4 c, float s) {
    float2 a = make_float2(c.x, c.y);
    float2 b = make_float2(c.z, c.w);
    __nv_fp8x2_storage_t p0 = __nv_cvt_float2_to_fp8x2(a, __NV_SATFINITE, __NV_E4M3);
    __nv_fp8x2_storage_t p1 = __nv_cvt_float2_to_fp8x2(b, __NV_SATFINITE, __NV_E4M3);
    __half2_raw h0 = __nv_cvt_fp8x2_to_halfraw2(p0, __NV_E4M3);
    __half2_raw h1 = __nv_cvt_fp8x2_to_halfraw2(p1, __NV_E4M3);
    float2 f0 = __half22float2(*reinterpret_cast<__half2*>(&h0));
    float2 f1 = __half22float2(*reinterpret_cast<__half2*>(&h1));
    f0.x *= s; f0.y *= s; f1.x *= s; f1.y *= s;
    __nv_bfloat162 bb0 = __float22bfloat162_rn(f0);
    __nv_bfloat162 bb1 = __float22bfloat162_rn(f1);
    uint2 r;
    r.x = *reinterpret_cast<unsigned*>(&bb0);
    r.y = *reinterpret_cast<unsigned*>(&bb1);
    return r;
}

// bf16x2 word -> two exact f32 (bf16 value = upper 16 bits of f32)
__device__ __forceinline__ float bflo(unsigned u) { return __uint_as_float(u << 16); }
__device__ __forceinline__ float bfhi(unsigned u) { return __uint_as_float(u & 0xFFFF0000u); }

__global__ void __launch_bounds__(128)
attn_fused_kernel(const float* __restrict__ q, const float* __restrict__ knew,
                  const float* __restrict__ vnew, const float* __restrict__ kcache,
                  const float* __restrict__ vcache, const float* __restrict__ kscale_p,
                  const float* __restrict__ vscale_p, const int* __restrict__ btab,
                  const int* __restrict__ clen, float* __restrict__ out)
{
    const int split = blockIdx.x;
    const int h     = blockIdx.y;
    const int s     = blockIdx.z;
    const int ctx   = clen[s];
    const int c0    = split * CHUNK;
    const int nsp   = (ctx + CHUNK - 1) / CHUNK;   // active splits for this seq
    if (split >= nsp) return;
    const int nvalid = min(CHUNK, ctx - c0);
    const int ntile  = (nvalid + TILE - 1) / TILE;

    __shared__ unsigned short kt[TILE][ROWB];   // dequantized K tile (bf16)
    __shared__ unsigned short vt[TILE][ROWB];   // dequantized V tile (bf16)
    __shared__ float qs[GQ * HDIM];
    __shared__ int   s_last;

    const int t = threadIdx.x;
    const int w = t >> 5;     // warp = query head within GQA group
    const int l = t & 31;     // lane

    // stage Q (512 floats, raw f32 as in reference)
    ((float4*)qs)[t] = ((const float4*)(q + (size_t)s * (NHEAD * HDIM)
                                          + (size_t)h * (GQ * HDIM)))[t];
    const float ks = kscale_p[h];
    const float vs = vscale_p[h];

    // hoist the chunk's 8 cache-block indices (independent LDGs, once per CTA)
    int blkArr[CHUNK / BSZ];
    #pragma unroll
    for (int j = 0; j < CHUNK / BSZ; ++j)
        blkArr[j] = btab[s * MBLK + (c0 >> 4) + j];

    float  m    = NEG_BIG;
    float  lsum = 0.f;
    float4 o    = make_float4(0.f, 0.f, 0.f, 0.f);

    for (int tb = 0; tb < ntile; ++tb) {
        const int base = c0 + tb * TILE;

        // ---- stage + dequantize K/V tile: warp w loads rows (i*4 + w), 512B rows coalesced
        #pragma unroll
        for (int i = 0; i < 8; ++i) {
            const int pl = i * 4 + w;          // tile-local position 0..31
            const int P  = base + pl;          // global position (< 2048 always: safe loads)
            const long long blk  = (long long)blkArr[tb * 2 + (pl >> 4)];
            const long long roff = ((blk * BSZ + (P & 15)) * NKVH + h) * (long long)HDIM;
            float4 kv = ((const float4*)(kcache + roff))[l];
            float4 vv = ((const float4*)(vcache + roff))[l];
            if (P == ctx - 1) {  // new token: reference scatters fp8(x/scale) at this slot
                const float* kp = knew + (size_t)s * (NKVH * HDIM) + h * HDIM + l * 4;
                const float* vp = vnew + (size_t)s * (NKVH * HDIM) + h * HDIM + l * 4;
                kv.x = __fdiv_rn(kp[0], ks); kv.y = __fdiv_rn(kp[1], ks);
                kv.z = __fdiv_rn(kp[2], ks); kv.w = __fdiv_rn(kp[3], ks);
                vv.x = __fdiv_rn(vp[0], vs); vv.y = __fdiv_rn(vp[1], vs);
                vv.z = __fdiv_rn(vp[2], vs); vv.w = __fdiv_rn(vp[3], vs);
            }
            *(uint2*)&kt[pl][l * 4] = dq4_bf(kv, ks);
            *(uint2*)&vt[pl][l * 4] = dq4_bf(vv, vs);
        }
        __syncthreads();

        // ---- scores: warp w = head w, lane l = position l (row l of K, 8 bf16 per LDS.128)
        float4 acc = make_float4(0.f, 0.f, 0.f, 0.f);
        #pragma unroll
        for (int d8 = 0; d8 < 16; ++d8) {
            const uint4  kq = *(const uint4*)&kt[l][d8 * 8];
            const float4 qa = *(const float4*)&qs[w * HDIM + d8 * 8];
            const float4 qb = *(const float4*)&qs[w * HDIM + d8 * 8 + 4];
            acc.x += bflo(kq.x) * qa.x; acc.y += bfhi(kq.x) * qa.y;
            acc.z += bflo(kq.y) * qa.z; acc.w += bfhi(kq.y) * qa.w;
            acc.x += bflo(kq.z) * qb.x; acc.y += bfhi(kq.z) * qb.y;
            acc.z += bflo(kq.w) * qb.z; acc.w += bfhi(kq.w) * qb.w;
        }
        float sc = ((acc.x + acc.y) + (acc.z + acc.w)) * ATTN_SCALE;
        if (base + l >= ctx) sc = NEG_BIG;

        // online softmax (per warp)
        float tm = sc;
        #pragma unroll
        for (int off = 16; off > 0; off >>= 1)
            tm = fmaxf(tm, __shfl_xor_sync(0xFFFFFFFFu, tm, off));
        const float mnew  = fmaxf(m, tm);
        const float alpha = __expf(m - mnew);
        const float p     = __expf(sc - mnew);   // masked lanes underflow to 0
        float tsum = p;
        #pragma unroll
        for (int off = 16; off > 0; off >>= 1)
            tsum += __shfl_xor_sync(0xFFFFFFFFu, tsum, off);
        lsum = lsum * alpha + tsum;
        m = mnew;

        // ---- accumulate O: lane l owns dims 4l..4l+3; weights broadcast by shuffle
        o.x *= alpha; o.y *= alpha; o.z *= alpha; o.w *= alpha;
        #pragma unroll
        for (int pp = 0; pp < 32; ++pp) {
            const float wgt = __shfl_sync(0xFFFFFFFFu, p, pp);
            const uint2 vq  = *(const uint2*)&vt[pp][l * 4];
            o.x += wgt * bflo(vq.x); o.y += wgt * bfhi(vq.x);
            o.z += wgt * bflo(vq.y); o.w += wgt * bfhi(vq.y);
        }
        __syncthreads();
    }

    // ---- publish partials
    *(float4*)&g_po[s][h][split][w][l * 4] = o;
    if (l == 0) { g_pm[s][h][split][w] = m; g_pl[s][h][split][w] = lsum; }
    __threadfence();
    __syncthreads();

    // ---- last-CTA-per-(s,h) detection (threadFenceReduction pattern)
    if (t == 0) {
        const int old = atomicAdd(&g_cnt[s][h], 1);
        int last = (old == nsp - 1);
        if (last) g_cnt[s][h] = 0;     // restore for next graph replay (deterministic)
        s_last = last;
    }
    __syncthreads();
    if (!s_last) return;
    __threadfence();

    // ---- in-place combine for this (s,h): warp w = GQA sub-head, L2-resident reads
    const float mi = (l < nsp) ? g_pm[s][h][l][w] : NEG_BIG;
    const float li = (l < nsp) ? g_pl[s][h][l][w] : 0.f;
    float M = mi;
    #pragma unroll
    for (int off = 16; off > 0; off >>= 1)
        M = fmaxf(M, __shfl_xor_sync(0xFFFFFFFFu, M, off));
    const float wi = __expf(mi - M);     // 0 for inactive lanes
    float L = wi * li;
    #pragma unroll
    for (int off = 16; off > 0; off >>= 1)
        L += __shfl_xor_sync(0xFFFFFFFFu, L, off);

    float4 acc = make_float4(0.f, 0.f, 0.f, 0.f);
    #pragma unroll
    for (int i = 0; i < NSPLIT; ++i) {
        if (i < nsp) {
            const float wgt = __shfl_sync(0xFFFFFFFFu, wi, i);
            const float4 pv = *(const float4*)&g_po[s][h][i][w][l * 4];
            acc.x += wgt * pv.x; acc.y += wgt * pv.y;
            acc.z += wgt * pv.z; acc.w += wgt * pv.w;
        }
    }
    const float inv = 1.f / L;
    float4 r = make_float4(acc.x * inv, acc.y * inv, acc.z * inv, acc.w * inv);
    *(float4*)(out + (size_t)s * (NHEAD * HDIM)
                   + (size_t)(h * GQ + w) * HDIM + l * 4) = r;
}

extern "C" void kernel_launch(void* const* d_in, const int* in_sizes, int n_in,
                              void* d_out, int out_size) {
    (void)in_sizes; (void)n_in; (void)out_size;
    const float* q    = (const float*)d_in[0];
    const float* k    = (const float*)d_in[1];
    const float* v    = (const float*)d_in[2];
    const float* kc   = (const float*)d_in[3];
    const float* vc   = (const float*)d_in[4];
    const float* ksc  = (const float*)d_in[5];
    const float* vsc  = (const float*)d_in[6];
    // d_in[7] slot_mapping: unused (position ctx-1 substitution is equivalent)
    const int*   btab = (const int*)d_in[8];   // JAX x64 disabled -> int32
    const int*   clen = (const int*)d_in[9];

    dim3 g1(NSPLIT, NKVH, S_N);
    attn_fused_kernel<<<g1, 128>>>(q, k, v, kc, vc, ksc, vsc, btab, clen, (float*)d_out);
}